// round 5
// baseline (speedup 1.0000x reference)
#include <cuda_runtime.h>
#include <math.h>

// ---------------- problem constants ----------------
#define NE    512        // num atoms
#define DIM   64         // embedding dim
#define NSIG  32768      // total signals (L*B = 1024*32)
#define SPAR  5          // sparsity level
#define SPC   64         // signals per CTA
#define NTHR  256        // threads per CTA (8 warps, 8 signals/warp)
#define RSTR  68         // residual smem row stride (padded)

#define Z_ELEMS   2097152          // 32*64*32*32
#define LOSS_OFF  Z_ELEMS
#define COEF_OFF  (Z_ELEMS + 1)
#define COEF_ELEMS (NE * NSIG)     // 16777216

// smem layout (floats): Ds[32768] Rs[64*68] dds[512] | Mask[1024 u32] SelJ[320] SelA[320] ssew[8]
#define SMEM_BYTES ((DIM*NE + SPC*RSTR + NE) * 4 + SPC*16*4 + SPC*SPAR*4*2 + 8*4)

// ---------------- device globals (no cudaMalloc allowed) ----------------
__device__ float  g_Dn[DIM * NE];
__device__ float  g_dd[NE];
__device__ double g_sse;

// ---------------- prep: normalize dictionary, column norms, zero sse ----------------
__global__ void prep_kernel(const float* __restrict__ D) {
    int j = threadIdx.x;              // one thread per atom, 512 threads
    if (j == 0) g_sse = 0.0;
    float s = 0.f;
    #pragma unroll
    for (int k = 0; k < DIM; k++) { float v = D[k * NE + j]; s = fmaf(v, v, s); }
    float nm = fmaxf(sqrtf(s), 1e-10f);
    float s2 = 0.f;
    #pragma unroll
    for (int k = 0; k < DIM; k++) {
        float v = D[k * NE + j] / nm;     // division to match reference numerics
        g_Dn[k * NE + j] = v;
        s2 = fmaf(v, v, s2);
    }
    g_dd[j] = s2;
}

// ---------------- zero-fill coefficients (+loss slot) ----------------
__global__ void zero_kernel(float4* __restrict__ p, int n4, float* __restrict__ tail) {
    int i = blockIdx.x * blockDim.x + threadIdx.x;
    int stride = gridDim.x * blockDim.x;
    float4 z = make_float4(0.f, 0.f, 0.f, 0.f);
    for (; i < n4; i += stride) p[i] = z;
    if (blockIdx.x == 0 && threadIdx.x == 0) *tail = 0.f;
}

// ---------------- main OMP kernel ----------------
__global__ void __launch_bounds__(NTHR, 1)
omp_kernel(const float* __restrict__ z_e, float* __restrict__ out) {
    extern __shared__ float sm[];
    float*    Ds   = sm;                              // [64][512]
    float*    Rs   = Ds + DIM * NE;                   // [64 signals][68]
    float*    dds  = Rs + SPC * RSTR;                 // [512]
    unsigned* Mask = (unsigned*)(dds + NE);           // [64][16] bitmask, 1 = available
    int*      SelJ = (int*)(Mask + SPC * 16);         // [64][5]
    float*    SelA = (float*)(SelJ + SPC * SPAR);     // [64][5]
    float*    ssew = SelA + SPC * SPAR;               // [8]

    const int tid   = threadIdx.x;
    const int cta   = blockIdx.x;
    const int batch = cta & 31;                 // 0..31
    const int lbase = (cta >> 5) * SPC;         // 0..960, this CTA's 64 consecutive l

    // ---- load dictionary into smem (float4, coalesced) ----
    {
        const float4* g4 = (const float4*)g_Dn;
        float4* s4 = (float4*)Ds;
        for (int i = tid; i < (DIM * NE) / 4; i += NTHR) s4[i] = g4[i];
    }
    for (int i = tid; i < NE; i += NTHR) dds[i] = g_dd[i];
    for (int i = tid; i < SPC * 16; i += NTHR) Mask[i] = 0xFFFFFFFFu;

    // ---- residual init: R[lo][k] = z_e[batch, k, lbase+lo] (coalesced global reads) ----
    {
        const float* zb = z_e + (size_t)batch * (DIM * 1024) + lbase;
        for (int i = tid; i < SPC * DIM; i += NTHR) {
            int k = i >> 6, lo = i & 63;
            Rs[lo * RSTR + k] = zb[k * 1024 + lo];
        }
    }
    __syncthreads();

    const int warp = tid >> 5, lane = tid & 31;
    const int b0 = warp * 8;                     // this warp's 8 signals: b0..b0+7

    // ================= 5 OMP iterations =================
    for (int it = 0; it < SPAR; it++) {
        float bAbs[8], bVal[8]; int bJ[8];
        #pragma unroll
        for (int b = 0; b < 8; b++) { bAbs[b] = -1.f; bVal[b] = 0.f; bJ[b] = 0; }

        // ---- corr = Dn^T r, streamed: lane owns atoms j = 4*lane + 128*tp + i ----
        #pragma unroll 1
        for (int tp = 0; tp < 4; tp++) {
            const int j0 = 4 * lane + 128 * tp;
            float acc[4][8];
            #pragma unroll
            for (int i = 0; i < 4; i++)
                #pragma unroll
                for (int b = 0; b < 8; b++) acc[i][b] = 0.f;

            const float* dscol = Ds + j0;
            #pragma unroll 8
            for (int k = 0; k < DIM; k++) {
                float4 d = *(const float4*)(dscol + k * NE);   // conflict-free LDS.128
                float r[8];
                #pragma unroll
                for (int b = 0; b < 8; b++) r[b] = Rs[(b0 + b) * RSTR + k];  // broadcast
                #pragma unroll
                for (int b = 0; b < 8; b++) {
                    acc[0][b] = fmaf(d.x, r[b], acc[0][b]);
                    acc[1][b] = fmaf(d.y, r[b], acc[1][b]);
                    acc[2][b] = fmaf(d.z, r[b], acc[2][b]);
                    acc[3][b] = fmaf(d.w, r[b], acc[3][b]);
                }
            }

            // ---- local candidate update (scan j ascending -> first-index tiebreak) ----
            const int w  = j0 >> 5;            // mask word (same for i=0..3)
            const int sh = j0 & 31;            // <= 28
            #pragma unroll
            for (int b = 0; b < 8; b++) {
                unsigned m = Mask[(b0 + b) * 16 + w] >> sh;
                #pragma unroll
                for (int i = 0; i < 4; i++) {
                    if ((m >> i) & 1u) {
                        float v = acc[i][b];
                        float a = fabsf(v);
                        if (a > bAbs[b]) { bAbs[b] = a; bVal[b] = v; bJ[b] = j0 + i; }
                    }
                }
            }
        }

        // ---- warp argmax per signal (|corr| max, lowest index on tie) ----
        #pragma unroll
        for (int b = 0; b < 8; b++) {
            #pragma unroll
            for (int off = 16; off; off >>= 1) {
                float oa = __shfl_xor_sync(0xffffffffu, bAbs[b], off);
                float ov = __shfl_xor_sync(0xffffffffu, bVal[b], off);
                int   oj = __shfl_xor_sync(0xffffffffu, bJ[b],  off);
                if (oa > bAbs[b] || (oa == bAbs[b] && oj < bJ[b])) {
                    bAbs[b] = oa; bVal[b] = ov; bJ[b] = oj;
                }
            }
        }

        // ---- alpha = corr[idx] / (||d_idx||^2 + eps) ----
        float alpha[8];
        #pragma unroll
        for (int b = 0; b < 8; b++) alpha[b] = bVal[b] / (dds[bJ[b]] + 1e-10f);

        if (lane == 0) {
            #pragma unroll
            for (int b = 0; b < 8; b++) {
                int j = bJ[b];
                Mask[(b0 + b) * 16 + (j >> 5)] &= ~(1u << (j & 31));
                SelJ[(b0 + b) * SPAR + it] = j;
                SelA[(b0 + b) * SPAR + it] = alpha[b];
            }
        }

        // ---- residual update: r -= d_idx * alpha (sequential per signal, like ref) ----
        #pragma unroll
        for (int b = 0; b < 8; b++) {
            int j = bJ[b]; float a = alpha[b];
            Rs[(b0 + b) * RSTR + lane]      -= Ds[lane * NE + j] * a;
            Rs[(b0 + b) * RSTR + lane + 32] -= Ds[(lane + 32) * NE + j] * a;
        }
        __syncwarp();
    }

    // ================= outputs =================
    // coefficients scatter (5 nonzeros per signal)
    {
        float* coeffs = out + COEF_OFF;
        if (lane < 8) {
            int bl = b0 + lane;
            int s  = (lbase + bl) * 32 + batch;       // token index l*B + batch
            #pragma unroll
            for (int t = 0; t < SPAR; t++) {
                coeffs[(size_t)SelJ[bl * SPAR + t] * NSIG + s] = SelA[bl * SPAR + t];
            }
        }
    }

    // reconstruction z = sum alpha_t * d_{j_t}; sse from final residual; stage z in Rs
    float sse = 0.f;
    #pragma unroll
    for (int b = 0; b < 8; b++) {
        int bl = b0 + b;
        float z0 = 0.f, z1 = 0.f;
        #pragma unroll
        for (int t = 0; t < SPAR; t++) {
            int j = SelJ[bl * SPAR + t]; float a = SelA[bl * SPAR + t];
            z0 = fmaf(Ds[lane * NE + j],        a, z0);
            z1 = fmaf(Ds[(lane + 32) * NE + j], a, z1);
        }
        float r0 = Rs[bl * RSTR + lane];
        float r1 = Rs[bl * RSTR + lane + 32];
        sse += r0 * r0 + r1 * r1;                 // (z_dl - z_e) == -residual
        Rs[bl * RSTR + lane]      = z0;
        Rs[bl * RSTR + lane + 32] = z1;
    }
    #pragma unroll
    for (int off = 16; off; off >>= 1) sse += __shfl_xor_sync(0xffffffffu, sse, off);
    if (lane == 0) ssew[warp] = sse;
    __syncthreads();
    if (tid == 0) {
        float tot = 0.f;
        #pragma unroll
        for (int w2 = 0; w2 < 8; w2++) tot += ssew[w2];
        atomicAdd(&g_sse, (double)tot);
    }

    // coalesced z_dl_out store: out[batch*65536 + k*1024 + lbase+lo]
    {
        float* zo = out + (size_t)batch * (DIM * 1024) + lbase;
        for (int i = tid; i < SPC * DIM; i += NTHR) {
            int k = i >> 6, lo = i & 63;
            zo[k * 1024 + lo] = Rs[lo * RSTR + k];
        }
    }
}

// ---------------- finish: loss = 1.25 * mean((z_dl - z_e)^2) ----------------
__global__ void finish_kernel(float* __restrict__ out) {
    out[LOSS_OFF] = (float)(1.25 * g_sse / (double)Z_ELEMS);
}

// ---------------- launch ----------------
extern "C" void kernel_launch(void* const* d_in, const int* in_sizes, int n_in,
                              void* d_out, int out_size) {
    const float* z_e = (const float*)d_in[0];
    const float* D   = (const float*)d_in[1];
    if (n_in >= 2 && in_sizes[0] == DIM * NE && in_sizes[1] == Z_ELEMS) {
        // defensive: swap if metadata order differs
        const float* t = z_e; z_e = D; D = t;
    }
    float* out = (float*)d_out;

    cudaFuncSetAttribute(omp_kernel, cudaFuncAttributeMaxDynamicSharedMemorySize, SMEM_BYTES);

    prep_kernel<<<1, NE>>>(D);

    // zero [loss slot + coefficients] = 16777217 floats starting at out+Z_ELEMS (16B aligned)
    {
        int n4 = (COEF_ELEMS) / 4;   // 4194304 float4; +1 scalar tail
        zero_kernel<<<1024, 256>>>((float4*)(out + Z_ELEMS), n4,
                                   out + Z_ELEMS + (size_t)n4 * 4);
    }

    omp_kernel<<<512, NTHR, SMEM_BYTES>>>(z_e, out);

    finish_kernel<<<1, 1>>>(out);
}

// round 6
// speedup vs baseline: 3.1460x; 3.1460x over previous
#include <cuda_runtime.h>
#include <math.h>

// ---------------- problem constants ----------------
#define NE     512        // num atoms
#define DIM    64         // embedding dim
#define NSIG   32768      // total signals (L*B = 1024*32)
#define SPAR   5          // sparsity level
#define NTHR   256        // threads per CTA (8 warps)
#define SPW    4          // signals per warp
#define SPT    32         // signals per tile (8 warps * 4)
#define NTILES 1024       // 32768 / 32
#define DSTR   516        // Ds smem row stride (pad: column reads 4-way instead of 32-way)
#define GRID_MAIN 148

#define Z_ELEMS   2097152          // 32*64*32*32
#define LOSS_OFF  Z_ELEMS
#define COEF_OFF  (Z_ELEMS + 1)
#define COEF_ELEMS (NE * NSIG)     // 16777216

// smem floats: Ds[64][516] XsT[64][32] dd[512] SelJ[160] SelA[160]
#define SMEM_FLOATS (DIM*DSTR + DIM*SPT + NE + SPT*SPAR*2)
#define SMEM_BYTES  (SMEM_FLOATS * 4)

// ---------------- device globals (no cudaMalloc allowed) ----------------
__device__ float  g_Dn[DIM * NE];       // normalized dict, row-major [k][j]
__device__ float  g_dd[NE];             // ||d_j||^2 (post-normalize)
__device__ float  g_G[NE * NE];         // Gram, row-major [j][j']
__device__ double g_sse;

// ---------------- f32x2 packed helpers ----------------
__device__ __forceinline__ unsigned long long pk2(float a, float b) {
    unsigned long long r;
    asm("mov.b64 %0, {%1, %2};" : "=l"(r) : "f"(a), "f"(b));
    return r;
}
__device__ __forceinline__ void fma2(unsigned long long& c,
                                     unsigned long long a, unsigned long long b) {
    asm("fma.rn.f32x2 %0, %1, %2, %0;" : "+l"(c) : "l"(a), "l"(b));
}
__device__ __forceinline__ float f2lo(unsigned long long v) { return __uint_as_float((unsigned)v); }
__device__ __forceinline__ float f2hi(unsigned long long v) { return __uint_as_float((unsigned)(v >> 32)); }

// ---------------- prep: normalize dictionary, column norms, zero sse ----------------
__global__ void prep_kernel(const float* __restrict__ D) {
    int j = threadIdx.x;                  // one thread per atom, 512 threads
    if (j == 0) g_sse = 0.0;
    float s = 0.f;
    #pragma unroll
    for (int k = 0; k < DIM; k++) { float v = D[k * NE + j]; s = fmaf(v, v, s); }
    float nm = fmaxf(sqrtf(s), 1e-10f);
    float s2 = 0.f;
    #pragma unroll
    for (int k = 0; k < DIM; k++) {
        float v = D[k * NE + j] / nm;     // division matches reference numerics
        g_Dn[k * NE + j] = v;
        s2 = fmaf(v, v, s2);
    }
    g_dd[j] = s2;
}

// ---------------- Gram: G[j][j'] = <d_j, d_j'> ----------------
__global__ void gram_kernel() {
    __shared__ float cols[8][DIM];        // 8 atoms' columns
    const int jb  = blockIdx.x * 8;
    const int tid = threadIdx.x;          // 256
    for (int i = tid; i < 8 * DIM; i += NTHR) {
        int jl = i & 7, k = i >> 3;
        cols[jl][k] = g_Dn[k * NE + jb + jl];
    }
    __syncthreads();
    float a[8], b[8];
    #pragma unroll
    for (int jl = 0; jl < 8; jl++) { a[jl] = 0.f; b[jl] = 0.f; }
    #pragma unroll 4
    for (int k = 0; k < DIM; k++) {
        float d1 = g_Dn[k * NE + tid];
        float d2 = g_Dn[k * NE + tid + 256];
        #pragma unroll
        for (int jl = 0; jl < 8; jl++) {
            a[jl] = fmaf(cols[jl][k], d1, a[jl]);
            b[jl] = fmaf(cols[jl][k], d2, b[jl]);
        }
    }
    #pragma unroll
    for (int jl = 0; jl < 8; jl++) {
        g_G[(jb + jl) * NE + tid]       = a[jl];
        g_G[(jb + jl) * NE + tid + 256] = b[jl];
    }
}

// ---------------- zero-fill coefficients (+loss slot) ----------------
__global__ void zero_kernel(float4* __restrict__ p, int n4, float* __restrict__ tail) {
    int i = blockIdx.x * blockDim.x + threadIdx.x;
    int stride = gridDim.x * blockDim.x;
    float4 z = make_float4(0.f, 0.f, 0.f, 0.f);
    for (; i < n4; i += stride) p[i] = z;
    if (blockIdx.x == 0 && threadIdx.x == 0) *tail = 0.f;
}

// ---------------- main persistent OMP kernel ----------------
__global__ void __launch_bounds__(NTHR, 1)
omp_kernel(const float* __restrict__ z_e, float* __restrict__ out) {
    extern __shared__ float sm[];
    float* Ds   = sm;                         // [64][516]
    float* XsT  = Ds + DIM * DSTR;            // [64][32]  transposed x: XsT[k][sig]
    float* dd   = XsT + DIM * SPT;            // [512]
    int*   SelJ = (int*)(dd + NE);            // [32][5]
    float* SelA = (float*)(SelJ + SPT * SPAR);// [32][5]

    const int tid  = threadIdx.x;
    const int warp = tid >> 5, lane = tid & 31;
    const int b0   = warp * SPW;              // this warp's 4 signals

    // ---- load dictionary into smem ONCE (persistent) ----
    for (int i4 = tid; i4 < (DIM * NE) / 4; i4 += NTHR) {
        int k = i4 >> 7, j4 = i4 & 127;
        ((float4*)(Ds + k * DSTR))[j4] = ((const float4*)g_Dn)[i4];
    }
    for (int i = tid; i < NE; i += NTHR) dd[i] = g_dd[i];

    double sse_acc = 0.0;

    for (int tile = blockIdx.x; tile < NTILES; tile += gridDim.x) {
        const int batch = tile & 31;
        const int lbase = (tile >> 5) * SPT;

        __syncthreads();   // previous-tile epilogue readers done before rewrite
        {
            const float* zb = z_e + (size_t)batch * (DIM * 1024) + lbase;
            for (int i = tid; i < SPT * DIM; i += NTHR) {
                int k = i >> 5, lo = i & 31;
                XsT[k * SPT + lo] = zb[k * 1024 + lo];
            }
        }
        __syncthreads();

        // ---- corr = Dn^T x, register-resident as f32x2 pairs ----
        // slot (tp,i): atom j = 128*tp + 4*lane + i; pair p=2tp+(i>>1), half=i&1
        unsigned long long c2[SPW][8];
        #pragma unroll
        for (int s = 0; s < SPW; s++)
            #pragma unroll
            for (int p = 0; p < 8; p++) c2[s][p] = 0ULL;

        {
            const float* dsl = Ds + 4 * lane;
            #pragma unroll 8
            for (int k = 0; k < DIM; k++) {
                float4 xv = *(const float4*)&XsT[k * SPT + b0];   // 4 signals' x[k]
                unsigned long long xp0 = pk2(xv.x, xv.x), xp1 = pk2(xv.y, xv.y);
                unsigned long long xp2 = pk2(xv.z, xv.z), xp3 = pk2(xv.w, xv.w);
                #pragma unroll
                for (int tp = 0; tp < 4; tp++) {
                    float4 d = *(const float4*)&dsl[k * DSTR + 128 * tp];
                    unsigned long long d01 = pk2(d.x, d.y), d23 = pk2(d.z, d.w);
                    fma2(c2[0][2*tp], d01, xp0); fma2(c2[0][2*tp+1], d23, xp0);
                    fma2(c2[1][2*tp], d01, xp1); fma2(c2[1][2*tp+1], d23, xp1);
                    fma2(c2[2][2*tp], d01, xp2); fma2(c2[2][2*tp+1], d23, xp2);
                    fma2(c2[3][2*tp], d01, xp3); fma2(c2[3][2*tp+1], d23, xp3);
                }
            }
        }

        // ---- 5 OMP selections via Gram recursion ----
        unsigned msk[SPW] = {0u, 0u, 0u, 0u};   // bit set = atom already selected

        for (int it = 0; it < SPAR; it++) {
            float bA[SPW], bV[SPW]; int bJ[SPW];
            #pragma unroll
            for (int s = 0; s < SPW; s++) {
                float ba = -1.f, bv = 0.f; int bj = 0;
                #pragma unroll
                for (int tp = 0; tp < 4; tp++) {
                    #pragma unroll
                    for (int pp = 0; pp < 2; pp++) {
                        unsigned long long v = c2[s][2*tp + pp];
                        int sl = tp * 4 + pp * 2;
                        float v0 = f2lo(v), v1 = f2hi(v);
                        if (!((msk[s] >> sl) & 1u)) {
                            float a = fabsf(v0);
                            if (a > ba) { ba = a; bv = v0; bj = 128*tp + 4*lane + 2*pp; }
                        }
                        if (!((msk[s] >> (sl + 1)) & 1u)) {
                            float a = fabsf(v1);
                            if (a > ba) { ba = a; bv = v1; bj = 128*tp + 4*lane + 2*pp + 1; }
                        }
                    }
                }
                bA[s] = ba; bV[s] = bv; bJ[s] = bj;
            }
            // warp argmax (|corr| max, lowest atom index on tie)
            #pragma unroll
            for (int s = 0; s < SPW; s++) {
                #pragma unroll
                for (int off = 16; off; off >>= 1) {
                    float oa = __shfl_xor_sync(0xffffffffu, bA[s], off);
                    float ov = __shfl_xor_sync(0xffffffffu, bV[s], off);
                    int   oj = __shfl_xor_sync(0xffffffffu, bJ[s], off);
                    if (oa > bA[s] || (oa == bA[s] && oj < bJ[s])) {
                        bA[s] = oa; bV[s] = ov; bJ[s] = oj;
                    }
                }
            }
            float alpha[SPW];
            #pragma unroll
            for (int s = 0; s < SPW; s++) {
                int j = bJ[s];
                alpha[s] = bV[s] / (dd[j] + 1e-10f);
                if (((j >> 2) & 31) == lane)                  // owning lane masks slot
                    msk[s] |= 1u << (((j >> 7) << 2) | (j & 3));
            }
            if (lane == 0) {
                #pragma unroll
                for (int s = 0; s < SPW; s++) {
                    SelJ[(b0 + s) * SPAR + it] = bJ[s];
                    SelA[(b0 + s) * SPAR + it] = alpha[s];
                }
            }
            if (it < SPAR - 1) {
                // corr -= alpha * G[:, j]  (G symmetric, row j coalesced)
                #pragma unroll
                for (int s = 0; s < SPW; s++) {
                    const float4* gr = (const float4*)(g_G + (size_t)bJ[s] * NE) + lane;
                    unsigned long long an = pk2(-alpha[s], -alpha[s]);
                    #pragma unroll
                    for (int tp = 0; tp < 4; tp++) {
                        float4 g = __ldg(gr + 32 * tp);
                        fma2(c2[s][2*tp],     pk2(g.x, g.y), an);
                        fma2(c2[s][2*tp + 1], pk2(g.z, g.w), an);
                    }
                }
            }
        }
        __syncthreads();   // SelJ/SelA visible to all warps

        // ---- epilogue: recon, z store, sse, coeff scatter ----
        {
            const int sig = lane;          // 32 lanes = 32 signals
            const int kb  = warp * 8;      // warp covers 8 dims
            int jj[SPAR]; float aa[SPAR];
            #pragma unroll
            for (int t = 0; t < SPAR; t++) {
                jj[t] = SelJ[sig * SPAR + t];
                aa[t] = SelA[sig * SPAR + t];
            }
            float* zo = out + (size_t)batch * (DIM * 1024) + lbase;
            float ssl = 0.f;
            #pragma unroll
            for (int kk = 0; kk < 8; kk++) {
                int k = kb + kk;
                float acc = 0.f;
                #pragma unroll
                for (int t = 0; t < SPAR; t++)
                    acc = fmaf(Ds[k * DSTR + jj[t]], aa[t], acc);
                float x    = XsT[k * SPT + sig];
                float diff = acc - x;                 // z_dl - z_e
                ssl = fmaf(diff, diff, ssl);
                zo[k * 1024 + sig] = x + diff;        // matches z_e + (z_dl - z_e)
            }
            sse_acc += (double)ssl;

            if (tid < SPT * SPAR) {                   // 160 scatter stores
                int sg = tid / SPAR, t = tid % SPAR;
                int sglob = (lbase + sg) * 32 + batch;
                out[COEF_OFF + (size_t)SelJ[sg * SPAR + t] * NSIG + sglob]
                    = SelA[sg * SPAR + t];
            }
        }
    }

    // ---- sse reduction ----
    #pragma unroll
    for (int off = 16; off; off >>= 1)
        sse_acc += __shfl_xor_sync(0xffffffffu, sse_acc, off);
    if (lane == 0) atomicAdd(&g_sse, sse_acc);
}

// ---------------- finish: loss = 1.25 * mean((z_dl - z_e)^2) ----------------
__global__ void finish_kernel(float* __restrict__ out) {
    out[LOSS_OFF] = (float)(1.25 * g_sse / (double)Z_ELEMS);
}

// ---------------- launch ----------------
extern "C" void kernel_launch(void* const* d_in, const int* in_sizes, int n_in,
                              void* d_out, int out_size) {
    const float* z_e = (const float*)d_in[0];
    const float* D   = (const float*)d_in[1];
    if (n_in >= 2 && in_sizes[0] == DIM * NE && in_sizes[1] == Z_ELEMS) {
        const float* t = z_e; z_e = D; D = t;   // defensive order swap
    }
    float* out = (float*)d_out;

    cudaFuncSetAttribute(omp_kernel, cudaFuncAttributeMaxDynamicSharedMemorySize, SMEM_BYTES);

    prep_kernel<<<1, NE>>>(D);
    gram_kernel<<<64, NTHR>>>();

    {   // zero [loss slot + coefficients]
        int n4 = COEF_ELEMS / 4;   // covers 16777216 floats from out+Z_ELEMS; +1 scalar tail
        zero_kernel<<<512, 256>>>((float4*)(out + Z_ELEMS), n4,
                                  out + Z_ELEMS + (size_t)n4 * 4);
    }

    omp_kernel<<<GRID_MAIN, NTHR, SMEM_BYTES>>>(z_e, out);

    finish_kernel<<<1, 1>>>(out);
}